// round 2
// baseline (speedup 1.0000x reference)
#include <cuda_runtime.h>

// LocalConv2DLayer: res[b,o,h,w] = sum_{c,i,j} m^2,
//   m = clamp(p-l,0,1)*clamp(r-p,0,1) * 4/(r-l)^2,  p = x[b,c,h+i,w+j]
// l,r are constant over taps (i,j)  =>  res = 5x5 box-sum of
//   S[b,o,h,w] = sum_c s_{o,c}(x[b,c,h,w]).
// Also r-l = 1/16 < 1, so the clamp-to-1 never binds when the product is
// nonzero:  s = (relu(v-l)*relu(r-v))^2 * (4/(r-l)^2)^2.

#define B_N   16
#define IC    3
#define OC    32
#define H_N   64
#define W_N   64
#define KS    5
#define NH    60
#define NW    60
#define NTHR  512
#define SSTR  68          // smem row stride (floats): multiple of 4, decorrelates banks

__global__ __launch_bounds__(NTHR, 4)
void localconv2d_kernel(const float* __restrict__ x,
                        const float* __restrict__ lb,
                        const float* __restrict__ rb,
                        float* __restrict__ out)
{
    const int o   = blockIdx.x;
    const int b   = blockIdx.y;
    const int tid = threadIdx.x;

    __shared__ float S [H_N * SSTR];   // pointwise channel-summed s
    __shared__ float Rh[H_N * SSTR];   // horizontal 5-tap sums

    // Per-(o,c) bounds: tap-(0,0) element of the broadcast [OC,IC,5,5] arrays.
    float l0[IC], r0[IC], n2[IC];
#pragma unroll
    for (int c = 0; c < IC; ++c) {
        float l = __ldg(lb + (o * IC + c) * (KS * KS));
        float r = __ldg(rb + (o * IC + c) * (KS * KS));
        float d  = r - l;
        float nc = 4.0f / (d * d);
        l0[c] = l; r0[c] = r; n2[c] = nc * nc;
    }

    const float* xb = x + (size_t)b * IC * H_N * W_N;

    // ---- Phase 1: S[h][w] = sum_c s(x[b,c,h,w]); 1024 float4 tasks ----
#pragma unroll
    for (int k = 0; k < 2; ++k) {
        int t  = tid + k * NTHR;          // 0..1023
        int h  = t >> 4;                  // 16 float4 per row
        int w4 = (t & 15) << 2;
        float a0 = 0.f, a1 = 0.f, a2 = 0.f, a3 = 0.f;
#pragma unroll
        for (int c = 0; c < IC; ++c) {
            float4 v = *reinterpret_cast<const float4*>(xb + (c * H_N + h) * W_N + w4);
            float l = l0[c], r = r0[c], nn = n2[c];
            float pa, pb, tt;
            pa = fmaxf(v.x - l, 0.f); pb = fmaxf(r - v.x, 0.f); tt = pa * pb; a0 = fmaf(tt * tt, nn, a0);
            pa = fmaxf(v.y - l, 0.f); pb = fmaxf(r - v.y, 0.f); tt = pa * pb; a1 = fmaf(tt * tt, nn, a1);
            pa = fmaxf(v.z - l, 0.f); pb = fmaxf(r - v.z, 0.f); tt = pa * pb; a2 = fmaf(tt * tt, nn, a2);
            pa = fmaxf(v.w - l, 0.f); pb = fmaxf(r - v.w, 0.f); tt = pa * pb; a3 = fmaf(tt * tt, nn, a3);
        }
        *reinterpret_cast<float4*>(&S[h * SSTR + w4]) = make_float4(a0, a1, a2, a3);
    }
    __syncthreads();

    // ---- Phase 2: horizontal 5-tap sums, 64 rows x 15 float4 segs = 960 tasks ----
#pragma unroll
    for (int k = 0; k < 2; ++k) {
        int t = tid + k * NTHR;
        if (t < H_N * 15) {
            int h  = t / 15;
            int w0 = (t - h * 15) << 2;
            const float* sr = &S[h * SSTR + w0];
            float4 u = *reinterpret_cast<const float4*>(sr);
            float4 v = *reinterpret_cast<const float4*>(sr + 4);
            float common = (u.y + u.z) + (u.w + v.x);     // a1+a2+a3+a4
            float o0 = u.x + common;
            float o1 = common + v.y;
            float o2 = (o1 + v.z) - u.y;
            float o3 = (o2 + v.w) - u.z;
            *reinterpret_cast<float4*>(&Rh[h * SSTR + w0]) = make_float4(o0, o1, o2, o3);
        }
    }
    __syncthreads();

    // ---- Phase 3: vertical 5-tap sums + store, 60 rows x 15 segs = 900 tasks ----
    float* ob = out + ((size_t)(b * OC + o)) * (NH * NW);
#pragma unroll
    for (int k = 0; k < 2; ++k) {
        int t = tid + k * NTHR;
        if (t < NH * 15) {
            int h  = t / 15;
            int w0 = (t - h * 15) << 2;
            const float* rr = &Rh[h * SSTR + w0];
            float4 r0v = *reinterpret_cast<const float4*>(rr);
            float4 r1v = *reinterpret_cast<const float4*>(rr + SSTR);
            float4 r2v = *reinterpret_cast<const float4*>(rr + 2 * SSTR);
            float4 r3v = *reinterpret_cast<const float4*>(rr + 3 * SSTR);
            float4 r4v = *reinterpret_cast<const float4*>(rr + 4 * SSTR);
            float4 s4;
            s4.x = ((r0v.x + r1v.x) + (r2v.x + r3v.x)) + r4v.x;
            s4.y = ((r0v.y + r1v.y) + (r2v.y + r3v.y)) + r4v.y;
            s4.z = ((r0v.z + r1v.z) + (r2v.z + r3v.z)) + r4v.z;
            s4.w = ((r0v.w + r1v.w) + (r2v.w + r3v.w)) + r4v.w;
            *reinterpret_cast<float4*>(ob + h * NW + w0) = s4;
        }
    }
}

extern "C" void kernel_launch(void* const* d_in, const int* in_sizes, int n_in,
                              void* d_out, int out_size)
{
    const float* x  = (const float*)d_in[0];
    const float* lb = (const float*)d_in[1];
    const float* rb = (const float*)d_in[2];
    float* out      = (float*)d_out;

    dim3 grid(OC, B_N);
    localconv2d_kernel<<<grid, NTHR>>>(x, lb, rb, out);
}